// round 7
// baseline (speedup 1.0000x reference)
#include <cuda_runtime.h>
#include <cuda_bf16.h>

// GNN_Attention: N=50000, E=800000, IN=8, ED=2, H=2, C=64, HID=64, OUT=2
#define MAXN 50000
#define MAXE 800000
#define HC   128
#define HID  64
#define NEG_SLOPE 0.2f

// -------- static device scratch --------
__device__ __align__(16) float g_xl[MAXN * HC];
__device__ __align__(16) float g_xr[MAXN * HC];
__device__ __align__(16) float g_expl[MAXE * 2];   // (p0,p1) per edge, CSR order
__device__ __align__(16) float g_dinv[MAXN];
__device__ __align__(16) float g_hacc[MAXN * HC];  // h = relu(msg/denom + bias)
__device__ __align__(16) float g_hw[MAXN * HID];

// CSR (sorted by dst)
__device__ int   g_cnt[MAXN + 1];
__device__ int   g_cur[MAXN];
__device__ int   g_row[MAXN + 1];
__device__ int   g_es_src[MAXE];
__device__ int   g_es_eid[MAXE];
__device__ __align__(16) float2 g_es_ea[MAXE];
__device__ float g_es_ew[MAXE];

// -------- 1. node projections + zero CSR counters --------
__global__ void k_proj(const float* __restrict__ x,
                       const float* __restrict__ Wl, const float* __restrict__ bl,
                       const float* __restrict__ Wr, const float* __restrict__ br,
                       int N) {
    int idx = blockIdx.x * blockDim.x + threadIdx.x;
    if (idx >= N * HC) return;
    if (idx < N + 1) g_cnt[idx] = 0;
    if (idx < N)     g_cur[idx] = 0;

    int n = idx >> 7, ch = idx & 127;
    const float* xv = x + n * 8;
    float sl = bl[ch], sr = br[ch];
    #pragma unroll
    for (int i = 0; i < 8; i++) {
        float xi = xv[i];
        sl += xi * Wl[ch * 8 + i];
        sr += xi * Wr[ch * 8 + i];
    }
    g_xl[idx] = sl;
    g_xr[idx] = sr;
}

// -------- 2. histogram of dst --------
__global__ void k_hist(const int* __restrict__ ei, int E) {
    int t = blockIdx.x * blockDim.x + threadIdx.x;
    if (t < E) atomicAdd(&g_cnt[ei[E + t]], 1);
}

// -------- 3. exclusive scan over counts -> row offsets (single block) ------
__global__ void k_scan(int N) {
    __shared__ int wsum[32];
    int t = threadIdx.x;              // 1024 threads
    int nb = blockDim.x;
    int CH = (N + nb - 1) / nb;
    int lo = t * CH, hi = min(lo + CH, N);
    int s = 0;
    for (int i = lo; i < hi; i++) s += g_cnt[i];
    int lane = t & 31, wid = t >> 5;
    int v = s;
    #pragma unroll
    for (int o = 1; o < 32; o <<= 1) {
        int u = __shfl_up_sync(0xffffffffu, v, o);
        if (lane >= o) v += u;
    }
    if (lane == 31) wsum[wid] = v;
    __syncthreads();
    if (wid == 0) {
        int xv = wsum[lane];
        #pragma unroll
        for (int o = 1; o < 32; o <<= 1) {
            int u = __shfl_up_sync(0xffffffffu, xv, o);
            if (lane >= o) xv += u;
        }
        wsum[lane] = xv;
    }
    __syncthreads();
    int excl = v - s + (wid > 0 ? wsum[wid - 1] : 0);
    int run = excl;
    for (int i = lo; i < hi; i++) { g_row[i] = run; run += g_cnt[i]; }
    if (hi == N) g_row[N] = run;   // == E (benign multi-write of same value)
}

// -------- 4. scatter edges into CSR order --------
__global__ void k_scatter(const int* __restrict__ ei,
                          const float* __restrict__ ea, int E) {
    int e = blockIdx.x * blockDim.x + threadIdx.x;
    if (e >= E) return;
    int dst = ei[E + e];
    int pos = g_row[dst] + atomicAdd(&g_cur[dst], 1);
    g_es_src[pos] = ei[e];
    g_es_eid[pos] = e;
    g_es_ea[pos]  = ((const float2*)ea)[e];
}

// -------- 5. GAT mainloop: one warp per dst node, register accumulation ----
// No atomics, no red: msg/denom live in registers; h stored once.
__global__ void k_gat(const float* __restrict__ We,
                      const float* __restrict__ att,
                      const float* __restrict__ gat_bias,
                      float* __restrict__ alpha_out, int N) {
    int w    = (blockIdx.x * blockDim.x + threadIdx.x) >> 5;
    int lane = threadIdx.x & 31;
    if (w >= N) return;
    int n = w;
    int r0 = g_row[n], r1 = g_row[n + 1];

    float4 at   = ((const float4*)att)[lane];
    float4 we01 = ((const float4*)We)[2 * lane];
    float4 we23 = ((const float4*)We)[2 * lane + 1];
    float4 xrv  = ((const float4*)g_xr)[n * 32 + lane];

    float4 macc = make_float4(0.f, 0.f, 0.f, 0.f);
    float dsum = 0.f;

    // 1-edge software prefetch
    int src_n = 0; float2 ea_n = make_float2(0.f, 0.f);
    float4 a_n = make_float4(0.f, 0.f, 0.f, 0.f);
    if (r0 < r1) {
        src_n = g_es_src[r0];
        ea_n  = g_es_ea[r0];
        a_n   = ((const float4*)g_xl)[src_n * 32 + lane];
    }
    for (int i = r0; i < r1; i++) {
        float2 eav = ea_n;
        float4 a   = a_n;
        if (i + 1 < r1) {
            src_n = g_es_src[i + 1];
            ea_n  = g_es_ea[i + 1];
            a_n   = ((const float4*)g_xl)[src_n * 32 + lane];
        }
        float e_0 = we01.x * eav.x + we01.y * eav.y;
        float e_1 = we01.z * eav.x + we01.w * eav.y;
        float e_2 = we23.x * eav.x + we23.y * eav.y;
        float e_3 = we23.z * eav.x + we23.w * eav.y;
        float z, s = 0.f;
        z = a.x + xrv.x + e_0; z = z > 0.f ? z : NEG_SLOPE * z; s += z * at.x;
        z = a.y + xrv.y + e_1; z = z > 0.f ? z : NEG_SLOPE * z; s += z * at.y;
        z = a.z + xrv.z + e_2; z = z > 0.f ? z : NEG_SLOPE * z; s += z * at.z;
        z = a.w + xrv.w + e_3; z = z > 0.f ? z : NEG_SLOPE * z; s += z * at.w;
        #pragma unroll
        for (int o = 8; o >= 1; o >>= 1)
            s += __shfl_xor_sync(0xffffffffu, s, o, 16);
        float p = __expf(s);                         // |logit| small: no max-sub
        float pd = __shfl_down_sync(0xffffffffu, p, 16);  // lane0 <- lane16's p
        if (lane == 0) ((float2*)g_expl)[i] = make_float2(p, pd);
        macc.x += p * a.x; macc.y += p * a.y;
        macc.z += p * a.z; macc.w += p * a.w;
        dsum += p;
    }
    float inv = dsum > 0.f ? __fdividef(1.f, dsum) : 0.f;
    float4 b4 = ((const float4*)gat_bias)[lane];
    float4 h;
    h.x = fmaxf(macc.x * inv + b4.x, 0.f);
    h.y = fmaxf(macc.y * inv + b4.y, 0.f);
    h.z = fmaxf(macc.z * inv + b4.z, 0.f);
    h.w = fmaxf(macc.w * inv + b4.w, 0.f);
    ((float4*)g_hacc)[n * 32 + lane] = h;

    // alpha / ew / deg (lane-parallel over the row)
    __threadfence_block();   // make lane0's g_expl writes visible to the warp
    float inv0 = __shfl_sync(0xffffffffu, inv, 0);
    float inv1 = __shfl_sync(0xffffffffu, inv, 16);
    float degs = 0.f;
    for (int i = r0 + lane; i < r1; i += 32) {
        float2 pe = ((const float2*)g_expl)[i];
        float a0 = pe.x * inv0, a1 = pe.y * inv1;
        ((float2*)alpha_out)[g_es_eid[i]] = make_float2(a0, a1);
        float ew = 0.5f * (a0 + a1);
        g_es_ew[i] = ew;
        degs += ew;
    }
    #pragma unroll
    for (int o = 16; o >= 1; o >>= 1)
        degs += __shfl_xor_sync(0xffffffffu, degs, o);
    if (lane == 0) g_dinv[n] = degs > 0.f ? rsqrtf(degs) : 0.f;
}

// -------- 6. pure tiled GEMM: g_hw = h @ gcn_W.T  (64 nodes, 4x4/thread) ---
#define NHB 64
#define WP  68
__global__ void k_node_hw(const float* __restrict__ gcn_W, int N) {
    __shared__ __align__(16) float Wsh[64 * WP];
    __shared__ __align__(16) float hsh[64 * WP];
    int t = threadIdx.x;                 // 256
    int base = blockIdx.x * NHB;

    int tx = t & 15;          // col group
    int ty = t >> 4;          // node group
    float acc[4][4];
    #pragma unroll
    for (int i = 0; i < 4; i++)
        #pragma unroll
        for (int j = 0; j < 4; j++) acc[i][j] = 0.f;

    #pragma unroll
    for (int ph = 0; ph < 2; ph++) {
        {
            int k = t & 63, cb = t >> 6;
            #pragma unroll
            for (int j = 0; j < 16; j++) {
                int c = cb + j * 4;
                Wsh[k * WP + c] = gcn_W[c * HC + ph * 64 + k];
            }
        }
        {
            int c = t & 63, nb = t >> 6;
            #pragma unroll
            for (int j = 0; j < 16; j++) {
                int nl = nb + j * 4;
                int n = base + nl;
                hsh[c * WP + nl] = (n < N) ? g_hacc[n * HC + ph * 64 + c] : 0.f;
            }
        }
        __syncthreads();
        #pragma unroll 4
        for (int k = 0; k < 64; k++) {
            float4 wv = *(const float4*)&Wsh[k * WP + tx * 4];
            float4 hv = *(const float4*)&hsh[k * WP + ty * 4];
            acc[0][0] += hv.x * wv.x; acc[0][1] += hv.x * wv.y;
            acc[0][2] += hv.x * wv.z; acc[0][3] += hv.x * wv.w;
            acc[1][0] += hv.y * wv.x; acc[1][1] += hv.y * wv.y;
            acc[1][2] += hv.y * wv.z; acc[1][3] += hv.y * wv.w;
            acc[2][0] += hv.z * wv.x; acc[2][1] += hv.z * wv.y;
            acc[2][2] += hv.z * wv.z; acc[2][3] += hv.z * wv.w;
            acc[3][0] += hv.w * wv.x; acc[3][1] += hv.w * wv.y;
            acc[3][2] += hv.w * wv.z; acc[3][3] += hv.w * wv.w;
        }
        __syncthreads();
    }
    #pragma unroll
    for (int i = 0; i < 4; i++) {
        int n = base + ty * 4 + i;
        if (n < N)
            ((float4*)g_hw)[n * 16 + tx] =
                make_float4(acc[i][0], acc[i][1], acc[i][2], acc[i][3]);
    }
}

// -------- 7. GCN aggregate + output head: one warp per dst node ------------
__global__ void k_gcn_out(const float* __restrict__ gcn_b,
                          const float* __restrict__ out_W,
                          const float* __restrict__ out_b,
                          float* __restrict__ out, int N) {
    int w    = (blockIdx.x * blockDim.x + threadIdx.x) >> 5;
    int lane = threadIdx.x & 31;
    if (w >= N) return;
    int n = w;
    int r0 = g_row[n], r1 = g_row[n + 1];
    float dinvn = g_dinv[n];

    float2 acc = make_float2(0.f, 0.f);
    int src_n = 0; float ew_n = 0.f, di_n = 0.f;
    float2 hv_n = make_float2(0.f, 0.f);
    if (r0 < r1) {
        src_n = g_es_src[r0];
        ew_n  = g_es_ew[r0];
        di_n  = g_dinv[src_n];
        hv_n  = ((const float2*)g_hw)[src_n * 32 + lane];
    }
    for (int i = r0; i < r1; i++) {
        float ew = ew_n, di = di_n;
        float2 hv = hv_n;
        if (i + 1 < r1) {
            src_n = g_es_src[i + 1];
            ew_n  = g_es_ew[i + 1];
            di_n  = g_dinv[src_n];
            hv_n  = ((const float2*)g_hw)[src_n * 32 + lane];
        }
        float nv = di * ew * dinvn;
        acc.x += nv * hv.x;
        acc.y += nv * hv.y;
    }
    float h0 = fmaxf(acc.x + gcn_b[2 * lane],     0.f);
    float h1 = fmaxf(acc.y + gcn_b[2 * lane + 1], 0.f);
    float s0 = h0 * out_W[2 * lane]      + h1 * out_W[2 * lane + 1];
    float s1 = h0 * out_W[64 + 2 * lane] + h1 * out_W[64 + 2 * lane + 1];
    #pragma unroll
    for (int o = 16; o >= 1; o >>= 1) {
        s0 += __shfl_down_sync(0xffffffffu, s0, o);
        s1 += __shfl_down_sync(0xffffffffu, s1, o);
    }
    if (lane == 0) {
        out[2 * n]     = s0 + out_b[0];
        out[2 * n + 1] = s1 + out_b[1];
    }
}

extern "C" void kernel_launch(void* const* d_in, const int* in_sizes, int n_in,
                              void* d_out, int out_size) {
    const float* x        = (const float*)d_in[0];
    const float* ea       = (const float*)d_in[1];
    const int*   ei       = (const int*)d_in[2];   // int32 (JAX x64 disabled)
    const float* Wl       = (const float*)d_in[3];
    const float* bl       = (const float*)d_in[4];
    const float* Wr       = (const float*)d_in[5];
    const float* br       = (const float*)d_in[6];
    const float* We       = (const float*)d_in[7];
    const float* att      = (const float*)d_in[8];
    const float* gat_bias = (const float*)d_in[9];
    const float* gcn_W    = (const float*)d_in[10];
    const float* gcn_b    = (const float*)d_in[11];
    const float* out_W    = (const float*)d_in[12];
    const float* out_b    = (const float*)d_in[13];

    int N = in_sizes[0] / 8;     // IN=8
    int E = in_sizes[1] / 2;     // ED=2

    float* out       = (float*)d_out;
    float* alpha_out = (float*)d_out + (size_t)N * 2;

    const int NT = 256;
    k_proj<<<(N * HC + NT - 1) / NT, NT>>>(x, Wl, bl, Wr, br, N);
    k_hist<<<(E + NT - 1) / NT, NT>>>(ei, E);
    k_scan<<<1, 1024>>>(N);
    k_scatter<<<(E + NT - 1) / NT, NT>>>(ei, ea, E);
    k_gat<<<(int)(((size_t)N * 32 + NT - 1) / NT), NT>>>(We, att, gat_bias, alpha_out, N);
    k_node_hw<<<(N + NHB - 1) / NHB, 256>>>(gcn_W, N);
    k_gcn_out<<<(int)(((size_t)N * 32 + NT - 1) / NT), NT>>>(gcn_b, out_W, out_b, out, N);
}